// round 13
// baseline (speedup 1.0000x reference)
#include <cuda_runtime.h>
#include <cstdint>
#include <cstddef>

#define DEV __device__ __forceinline__
#define HD __host__ __device__

static constexpr double kPI = 3.14159265358979323846;

// ---------------- constexpr math (compile-time tables) ----------------
HD constexpr double creduce(double x){
  while (x >  kPI) x -= 2.0 * kPI;
  while (x < -kPI) x += 2.0 * kPI;
  return x;
}
HD constexpr double csin(double x){
  x = creduce(x);
  double t = x, s = x, x2 = x * x;
  for (int i = 1; i < 26; ++i){ t *= -x2 / (double)((2*i) * (2*i + 1)); s += t; }
  return s;
}
HD constexpr double ccos(double x){
  x = creduce(x);
  double t = 1.0, s = 1.0, x2 = x * x;
  for (int i = 1; i < 26; ++i){ t *= -x2 / (double)((2*i - 1) * (2*i)); s += t; }
  return s;
}
HD constexpr double clog(double x){
  double r = x, k = 0.0;
  while (r > 1.25) { r *= 0.5; k += 1.0; }
  while (r < 0.75) { r *= 2.0; k -= 1.0; }
  double z = (r - 1.0) / (r + 1.0), z2 = z * z, term = z, s = z;
  for (int i = 1; i < 60; ++i){ term *= z2; s += term / (double)(2*i + 1); }
  return 2.0 * s + k * 0.69314718055994530942;
}

// ---------------- mel filterbank, 2-sparse per spectral bin ----------------
HD constexpr double hz2mel(double f){ return 1127.0 * clog(1.0 + f / 700.0); }
HD constexpr double mel_lo(){ return hz2mel(80.0); }
HD constexpr double mel_step(){ return (hz2mel(7600.0) - hz2mel(80.0)) / 81.0; }
HD constexpr double bin_mel(int k){ return hz2mel(8000.0 * (double)k / 64.0); }

struct MelEnt { int ja; int jb; float wa; float wb; };

HD constexpr MelEnt mel_ent(int k){
  MelEnt e{-1, -1, 0.0f, 0.0f};
  double u = (bin_mel(k) - mel_lo()) / mel_step();
  if (u <= 0.0 || u >= 81.0) return e;
  int i = (int)u;
  double scale = (k == 32 || k == 64) ? 2.0 : 1.0;
  double wu = ((double)(i + 1) - u) * scale;
  double wl = (u - (double)i) * scale;
  if (i - 1 >= 0 && i - 1 <= 79){ e.ja = i - 1; e.wa = (float)wu; }
  if (i <= 79){ e.jb = i; e.wb = (float)wl; }
  return e;
}
HD constexpr bool bin_used(int k){
  MelEnt e = mel_ent(k);
  return e.ja >= 0 || e.jb >= 0;
}

// Emission order = exact runtime order of the fused final loop (R7-proven):
// idx 0: bin 32; idx 1..60: r=1..15, sub order (r, 64-r, 32-r, 32+r); idx 61,62: bins 16, 48.
HD constexpr int emit_bin(int idx){
  if (idx == 0) return 32;
  if (idx <= 60){
    int r = (idx - 1) / 4 + 1, sub = (idx - 1) % 4;
    return sub == 0 ? r : sub == 1 ? 64 - r : sub == 2 ? 32 - r : 32 + r;
  }
  return idx == 61 ? 16 : 48;
}
HD constexpr int targ(int bin, int slot){
  MelEnt e = mel_ent(bin);
  return slot ? e.jb : e.ja;
}
HD constexpr int emit_pos(int bin){
  for (int idx = 0; idx < 63; ++idx) if (emit_bin(idx) == bin) return idx;
  return -1;
}
HD constexpr bool is_first_touch(int bin, int slot){
  int j = targ(bin, slot);
  if (j < 0) return false;
  int pos = emit_pos(bin);
  for (int idx = 0; idx < pos; ++idx){
    int b2 = emit_bin(idx);
    if (targ(b2, 0) == j || targ(b2, 1) == j) return false;
  }
  if (slot == 1 && targ(bin, 0) == j) return false;
  return true;
}
HD constexpr bool mel_used(int j){
  for (int idx = 0; idx < 63; ++idx){
    int b2 = emit_bin(idx);
    if (targ(b2, 0) == j || targ(b2, 1) == j) return true;
  }
  return false;
}
HD constexpr int bitrev6(int n){
  int r = 0;
  for (int b = 0; b < 6; ++b) r |= ((n >> b) & 1) << (5 - b);
  return r;
}

// pre-halved Hann window: 0.5 * (0.5 - 0.5*cos(2*pi*m/128))
HD constexpr float hwin(int m){
  return (float)(0.5 * (0.5 - 0.5 * ccos(2.0 * kPI * (double)m / 128.0)));
}

// ---------------- magnitude: MUFU.SQRT (p2 >= 0 always; sqrt.approx(0/denorm) = 0) ----
DEV float magf(float re, float im){
  float p2 = fmaf(re, re, im * im);
  float m;
  asm("sqrt.approx.f32 %0, %1;" : "=f"(m) : "f"(p2));
  return m;
}

// ---------------- mel scatter (static register indices, proven) ----------------
template<int BIN>
DEV void scatter(float* mel, float mag){
  constexpr MelEnt e = mel_ent(BIN);
  if constexpr (e.ja >= 0){
    if constexpr (is_first_touch(BIN, 0)) mel[e.ja] = e.wa * mag;
    else mel[e.ja] = fmaf(e.wa, mag, mel[e.ja]);
  }
  if constexpr (e.jb >= 0){
    if constexpr (is_first_touch(BIN, 1)) mel[e.jb] = e.wb * mag;
    else mel[e.jb] = fmaf(e.wb, mag, mel[e.jb]);
  }
}

// ---------------- fused window + bit-reversed load + stage-0, paired LDS.64 ----------
// bp2[s] aliases (x[t0+tid+2s], x[t0+tid+2s+1]) for this thread (alignment via sxe/sxo).
template<int M> struct Fused0 {
  static DEV void run(float* Ar, float* Ai, const float2* bp2){
    constexpr int s0 = bitrev6(2*M);
    constexpr int s1 = bitrev6(2*M + 1);          // = s0 + 32
    constexpr float w0r = hwin(2*s0), w0i = hwin(2*s0 + 1);
    constexpr float w1r = hwin(2*s1), w1i = hwin(2*s1 + 1);
    float2 a = bp2[s0];
    float2 b = bp2[s1];
    float tr = b.x * w1r;
    float ti = b.y * w1i;
    if constexpr (w0r == 0.0f){                   // only s0 == 0 (window zero at m=0)
      Ar[2*M]     = tr;
      Ar[2*M + 1] = -tr;
    } else {
      Ar[2*M]     = fmaf(a.x, w0r,  tr);
      Ar[2*M + 1] = fmaf(a.x, w0r, -tr);
    }
    Ai[2*M]     = fmaf(a.y, w0i,  ti);
    Ai[2*M + 1] = fmaf(a.y, w0i, -ti);
    Fused0<M + 1>::run(Ar, Ai, bp2);
  }
};
template<> struct Fused0<32>{ static DEV void run(float*, float*, const float2*){} };

// ---------------- radix-2 stage 1 (all twiddles trivial: 1 and -i) ----------------
template<int M> struct Stage1 {
  static DEV void run(float* Ar, float* Ai){
    constexpr int j  = M & 1;
    constexpr int i0 = ((M >> 1) << 2) + j;
    constexpr int i1 = i0 + 2;
    float br_ = Ar[i1], bi_ = Ai[i1];
    float tr, ti;
    if constexpr (j == 0){ tr = br_; ti = bi_; }
    else { tr = bi_; ti = -br_; }                 // w = -i
    float ar_ = Ar[i0], ai_ = Ai[i0];
    Ar[i0] = ar_ + tr; Ai[i0] = ai_ + ti;
    Ar[i1] = ar_ - tr; Ai[i1] = ai_ - ti;
    Stage1<M + 1>::run(Ar, Ai);
  }
};
template<> struct Stage1<32>{ static DEV void run(float*, float*){} };

// ---------------- radix-4 dragonfly: fuses radix-2 stages 2 and 3 ----------------
template<int S, int G> struct R4Loop {
  static DEV void run(float* Ar, float* Ai){
    constexpr int h  = 1 << S;
    constexpr int j  = G & (h - 1);
    constexpr int i0 = ((G >> S) << (S + 2)) + j;
    constexpr double ang = kPI * (double)j / (double)(2 * h);
    constexpr float c1 = (float)ccos(2.0 * ang), s1 = (float)csin(2.0 * ang);
    constexpr float c2 = (float)ccos(ang),        s2 = (float)csin(ang);
    constexpr float c3 = (float)ccos(3.0 * ang),  s3 = (float)csin(3.0 * ang);

    float x0r = Ar[i0],       x0i = Ai[i0];
    float x1r = Ar[i0 + h],   x1i = Ai[i0 + h];
    float x2r = Ar[i0 + 2*h], x2i = Ai[i0 + 2*h];
    float x3r = Ar[i0 + 3*h], x3i = Ai[i0 + 3*h];

    float u1r, u1i, u2r, u2i, u3r, u3i;
    if constexpr (j == 0){
      u1r = x2r; u1i = x2i; u2r = x1r; u2i = x1i; u3r = x3r; u3i = x3i;
    } else {
      u1r = fmaf(c2, x2r,  s2 * x2i);
      u1i = fmaf(c2, x2i, -(s2 * x2r));
      u3r = fmaf(c3, x3r,  s3 * x3i);
      u3i = fmaf(c3, x3i, -(s3 * x3r));
      if constexpr (2*j == h){
        u2r = x1i; u2i = -x1r;
      } else {
        u2r = fmaf(c1, x1r,  s1 * x1i);
        u2i = fmaf(c1, x1i, -(s1 * x1r));
      }
    }
    float r0r = x0r + u2r, r0i = x0i + u2i;
    float r1r = x0r - u2r, r1i = x0i - u2i;
    float pr  = u1r + u3r, pi  = u1i + u3i;
    float qr  = u1r - u3r, qi  = u1i - u3i;

    Ar[i0]       = r0r + pr;  Ai[i0]       = r0i + pi;
    Ar[i0 + 2*h] = r0r - pr;  Ai[i0 + 2*h] = r0i - pi;
    Ar[i0 + h]   = r1r + qi;  Ai[i0 + h]   = r1i - qr;
    Ar[i0 + 3*h] = r1r - qi;  Ai[i0 + 3*h] = r1i + qr;
    R4Loop<S, G + 1>::run(Ar, Ai);
  }
};
template<int S> struct R4Loop<S, 16>{ static DEV void run(float*, float*){} };

// ---------------- radix-2 stage 4 (h = 16) ----------------
template<int M> struct Stage4 {
  static DEV void run(float* Ar, float* Ai){
    constexpr int j  = M & 15;
    constexpr int i0 = ((M >> 4) << 5) + j;
    constexpr int i1 = i0 + 16;
    float br_ = Ar[i1], bi_ = Ai[i1];
    float tr, ti;
    if constexpr (j == 0){ tr = br_; ti = bi_; }
    else if constexpr (j == 8){ tr = bi_; ti = -br_; }
    else {
      constexpr float c = (float)ccos(kPI * (double)j / 16.0);
      constexpr float s = (float)csin(kPI * (double)j / 16.0);
      tr = fmaf(c, br_,  s * bi_);
      ti = fmaf(c, bi_, -(s * br_));
    }
    float ar_ = Ar[i0], ai_ = Ai[i0];
    Ar[i0] = ar_ + tr; Ai[i0] = ai_ + ti;
    Ar[i1] = ar_ - tr; Ai[i1] = ai_ - ti;
    Stage4<M + 1>::run(Ar, Ai);
  }
};
template<> struct Stage4<32>{ static DEV void run(float*, float*){} };

// ---------------- real-split + magnitude + mel scatter on explicit values ----------------
template<int K>
DEV void do_pair_v(float P, float Q, float R, float S, float* mel){
  float zer = P + R, zei = Q - S;
  float zor = Q + S, zoi = R - P;
  constexpr float c = (float)ccos(kPI * (double)K / 64.0);
  constexpr float s = (float)csin(kPI * (double)K / 64.0);
  float A  = fmaf(c, zor,  s * zoi);
  float Bv = fmaf(c, zoi, -(s * zor));
  scatter<K>(mel, magf(zer + A, zei + Bv));
  if constexpr (bin_used(64 - K)){
    scatter<64 - K>(mel, magf(zer - A, Bv - zei));
  }
}

// ---------------- fused stage-5 + real-split (R7-proven) ----------------
template<int R> struct Final {
  static DEV void run(float* Ar, float* Ai, float* mel){
    constexpr float c = (float)ccos(kPI * (double)R / 32.0);
    constexpr float s = (float)csin(kPI * (double)R / 32.0);
    float ar = Ar[R], ai = Ai[R], br = Ar[R+32], bi = Ai[R+32];
    float tr = fmaf(c, br,  s * bi);
    float ti = fmaf(c, bi, -(s * br));
    float zRr  = ar + tr, zRi  = ai + ti;          // Z[R]
    float zRpr = ar - tr, zRpi = ai - ti;          // Z[R+32]
    float a2r = Ar[32-R], a2i = Ai[32-R], b2r = Ar[64-R], b2i = Ai[64-R];
    float t2r = fmaf(-c, b2r,  s * b2i);
    float t2i = fmaf(-c, b2i, -(s * b2r));
    float zSr  = a2r + t2r, zSi  = a2i + t2i;      // Z[32-R]
    float zSpr = a2r - t2r, zSpi = a2i - t2i;      // Z[64-R]
    do_pair_v<R>     (zRr, zRi, zSpr, zSpi, mel);  // pair R: Z[R], Z[64-R]
    do_pair_v<32 - R>(zSr, zSi, zRpr, zRpi, mel);  // pair 32-R: Z[32-R], Z[32+R]
    Final<R + 1>::run(Ar, Ai, mel);
  }
};
template<> struct Final<16> {
  static DEV void run(float* Ar, float* Ai, float* mel){
    float ar = Ar[16], ai = Ai[16], br = Ar[48], bi = Ai[48];
    do_pair_v<16>(ar + bi, ai - br, ar - bi, ai + br, mel);   // w = -i
  }
};

// ---------------- store mel row to SMEM (untouched bins -> literal 0) ----------------
template<int J> struct StoreLoop {
  static DEV void run(float* dst, const float* mel){
    if constexpr (mel_used(J)) dst[J] = mel[J];
    else dst[J] = 0.0f;
    StoreLoop<J + 1>::run(dst, mel);
  }
};
template<> struct StoreLoop<80>{ static DEV void run(float*, const float*){} };

// ---------------- kernel ----------------
static constexpr int TPB = 128;       // one thread = one frame
static constexpr int NCOL = 81;       // 1 raw sample + 80 mel

__global__ void __launch_bounds__(TPB, 5)
mel_kernel(const float* __restrict__ x, float* __restrict__ out){
  __shared__ __align__(8) float sxe[256];         // x[t0 + i]
  __shared__ __align__(8) float sxo[256];         // x[t0 + 1 + i]  (shifted copy)
  __shared__ __align__(16) float sout[TPB * NCOL];

  const int tid = threadIdx.x;
  const int t0  = blockIdx.x * TPB;
  const float* xrow = x + (size_t)blockIdx.y * 16384;

  #pragma unroll
  for (int i = tid; i < 256; i += TPB){
    int t = t0 + i;
    sxe[i] = (t < 16384) ? xrow[t] : 0.0f;
    int t2 = t + 1;
    sxo[i] = (t2 < 16384) ? xrow[t2] : 0.0f;
  }
  __syncthreads();

  // Aligned float2 base: bp2[s] = (x[t0+tid+2s], x[t0+tid+2s+1]) for either tid parity.
  const float2* bp2 = (tid & 1) ? (const float2*)(sxo + (tid - 1))
                                : (const float2*)(sxe + tid);

  float Ar[64], Ai[64], mel[80];
  Fused0<0>::run(Ar, Ai, bp2);                    // window + bitrev load (LDS.64) + stage 0
  Stage1<0>::run(Ar, Ai);                         // stage 1 (trivial twiddles)
  R4Loop<2, 0>::run(Ar, Ai);                      // stages 2+3 fused radix-4
  Stage4<0>::run(Ar, Ai);                         // stage 4 radix-2
  // r = 0 of stage 5: Z[32] = pos0 - pos32 (w = 1); bin 0 excluded by mel matrix.
  scatter<32>(mel, magf(Ar[0] - Ar[32], Ai[0] - Ai[32]));
  Final<1>::run(Ar, Ai, mel);                     // fused stage-5 + realsplit + mag + mel

  // stage 81-float output row in SMEM (stride 81 -> bank-conflict-free)
  float* row = sout + tid * NCOL;
  row[0] = sxe[tid];
  StoreLoop<0>::run(row + 1, mel);
  __syncthreads();

  // Bulk async 1D store SMEM -> GMEM (contiguous 41472 B, 16B-aligned both sides).
  if (tid == 0){
    uint32_t sa;
    asm("{ .reg .u64 t; cvta.to.shared.u64 t, %1; cvt.u32.u64 %0, t; }"
        : "=r"(sa) : "l"(sout));
    float* gdst = out + ((size_t)blockIdx.y * 16384 + (size_t)t0) * NCOL;
    asm volatile("fence.proxy.async.shared::cta;" ::: "memory");
    asm volatile("cp.async.bulk.global.shared::cta.bulk_group [%0], [%1], %2;"
                 :: "l"(gdst), "r"(sa), "r"((uint32_t)(TPB * NCOL * 4)) : "memory");
    asm volatile("cp.async.bulk.commit_group;" ::: "memory");
    asm volatile("cp.async.bulk.wait_group 0;" ::: "memory");
  }
}

extern "C" void kernel_launch(void* const* d_in, const int* in_sizes, int n_in,
                              void* d_out, int out_size){
  (void)in_sizes; (void)n_in; (void)out_size;
  const float* x = (const float*)d_in[0];
  float* out = (float*)d_out;
  dim3 grid(16384 / TPB, 16);
  mel_kernel<<<grid, TPB>>>(x, out);
}

// round 14
// speedup vs baseline: 1.5268x; 1.5268x over previous
#include <cuda_runtime.h>
#include <cstdint>
#include <cstddef>

#define DEV __device__ __forceinline__
#define HD __host__ __device__

static constexpr double kPI = 3.14159265358979323846;

// ---------------- constexpr math (compile-time tables) ----------------
HD constexpr double creduce(double x){
  while (x >  kPI) x -= 2.0 * kPI;
  while (x < -kPI) x += 2.0 * kPI;
  return x;
}
HD constexpr double csin(double x){
  x = creduce(x);
  double t = x, s = x, x2 = x * x;
  for (int i = 1; i < 26; ++i){ t *= -x2 / (double)((2*i) * (2*i + 1)); s += t; }
  return s;
}
HD constexpr double ccos(double x){
  x = creduce(x);
  double t = 1.0, s = 1.0, x2 = x * x;
  for (int i = 1; i < 26; ++i){ t *= -x2 / (double)((2*i - 1) * (2*i)); s += t; }
  return s;
}
HD constexpr double clog(double x){
  double r = x, k = 0.0;
  while (r > 1.25) { r *= 0.5; k += 1.0; }
  while (r < 0.75) { r *= 2.0; k -= 1.0; }
  double z = (r - 1.0) / (r + 1.0), z2 = z * z, term = z, s = z;
  for (int i = 1; i < 60; ++i){ term *= z2; s += term / (double)(2*i + 1); }
  return 2.0 * s + k * 0.69314718055994530942;
}

// ---------------- mel filterbank, 2-sparse per spectral bin ----------------
HD constexpr double hz2mel(double f){ return 1127.0 * clog(1.0 + f / 700.0); }
HD constexpr double mel_lo(){ return hz2mel(80.0); }
HD constexpr double mel_step(){ return (hz2mel(7600.0) - hz2mel(80.0)) / 81.0; }
HD constexpr double bin_mel(int k){ return hz2mel(8000.0 * (double)k / 64.0); }

struct MelEnt { int ja; int jb; float wa; float wb; };

HD constexpr MelEnt mel_ent(int k){
  MelEnt e{-1, -1, 0.0f, 0.0f};
  double u = (bin_mel(k) - mel_lo()) / mel_step();
  if (u <= 0.0 || u >= 81.0) return e;
  int i = (int)u;
  double scale = (k == 32 || k == 64) ? 2.0 : 1.0;
  double wu = ((double)(i + 1) - u) * scale;
  double wl = (u - (double)i) * scale;
  if (i - 1 >= 0 && i - 1 <= 79){ e.ja = i - 1; e.wa = (float)wu; }
  if (i <= 79){ e.jb = i; e.wb = (float)wl; }
  return e;
}
HD constexpr bool bin_used(int k){
  MelEnt e = mel_ent(k);
  return e.ja >= 0 || e.jb >= 0;
}

// Emission order = exact runtime order of the fused final loop (R7-proven):
// idx 0: bin 32; idx 1..60: r=1..15, sub order (r, 64-r, 32-r, 32+r); idx 61,62: bins 16, 48.
HD constexpr int emit_bin(int idx){
  if (idx == 0) return 32;
  if (idx <= 60){
    int r = (idx - 1) / 4 + 1, sub = (idx - 1) % 4;
    return sub == 0 ? r : sub == 1 ? 64 - r : sub == 2 ? 32 - r : 32 + r;
  }
  return idx == 61 ? 16 : 48;
}
HD constexpr int targ(int bin, int slot){
  MelEnt e = mel_ent(bin);
  return slot ? e.jb : e.ja;
}
HD constexpr int emit_pos(int bin){
  for (int idx = 0; idx < 63; ++idx) if (emit_bin(idx) == bin) return idx;
  return -1;
}
HD constexpr bool is_first_touch(int bin, int slot){
  int j = targ(bin, slot);
  if (j < 0) return false;
  int pos = emit_pos(bin);
  for (int idx = 0; idx < pos; ++idx){
    int b2 = emit_bin(idx);
    if (targ(b2, 0) == j || targ(b2, 1) == j) return false;
  }
  if (slot == 1 && targ(bin, 0) == j) return false;
  return true;
}
HD constexpr bool mel_used(int j){
  for (int idx = 0; idx < 63; ++idx){
    int b2 = emit_bin(idx);
    if (targ(b2, 0) == j || targ(b2, 1) == j) return true;
  }
  return false;
}
HD constexpr int bitrev6(int n){
  int r = 0;
  for (int b = 0; b < 6; ++b) r |= ((n >> b) & 1) << (5 - b);
  return r;
}

// pre-halved Hann window: 0.5 * (0.5 - 0.5*cos(2*pi*m/128))
HD constexpr float hwin(int m){
  return (float)(0.5 * (0.5 - 0.5 * ccos(2.0 * kPI * (double)m / 128.0)));
}

// ---------------- imm-form FFMA arithmetic (rt_SMSP = 1 vs FADD's 2) ----------------
// a + b  ==  fma(a, 1.0, b)   (exact: a*1 exact, single rounding of a+b)
DEV float ADDI(float a, float b){
  float r;
  asm("fma.rn.f32 %0, %1, 0f3F800000, %2;" : "=f"(r) : "f"(a), "f"(b));
  return r;
}
// a - b  ==  fma(b, -1.0, a)
DEV float SUBI(float a, float b){
  float r;
  asm("fma.rn.f32 %0, %1, 0fBF800000, %2;" : "=f"(r) : "f"(b), "f"(a));
  return r;
}
// const * x as imm-form FFMA (addend -0 preserves sign of zero)
DEV float MULC(float x, float c){ return __fmaf_rn(x, c, -0.0f); }

// ---------------- magnitude: MUFU.SQRT (p2 >= 0 always; sqrt.approx(0/denorm) = 0) ----
DEV float magf(float re, float im){
  float p2 = fmaf(re, re, im * im);
  float m;
  asm("sqrt.approx.f32 %0, %1;" : "=f"(m) : "f"(p2));
  return m;
}

// ---------------- mel scatter (static register indices, proven) ----------------
template<int BIN>
DEV void scatter(float* mel, float mag){
  constexpr MelEnt e = mel_ent(BIN);
  if constexpr (e.ja >= 0){
    if constexpr (is_first_touch(BIN, 0)) mel[e.ja] = MULC(mag, e.wa);
    else mel[e.ja] = __fmaf_rn(mag, e.wa, mel[e.ja]);
  }
  if constexpr (e.jb >= 0){
    if constexpr (is_first_touch(BIN, 1)) mel[e.jb] = MULC(mag, e.wb);
    else mel[e.jb] = __fmaf_rn(mag, e.wb, mel[e.jb]);
  }
}

// ---------------- fused window + bit-reversed load + stage-0, paired LDS.64 ----------
// bp2[s] aliases (x[t0+tid+2s], x[t0+tid+2s+1]) for this thread (alignment via sxe/sxo).
template<int M> struct Fused0 {
  static DEV void run(float* Ar, float* Ai, const float2* bp2){
    constexpr int s0 = bitrev6(2*M);
    constexpr int s1 = bitrev6(2*M + 1);          // = s0 + 32
    constexpr float w0r = hwin(2*s0), w0i = hwin(2*s0 + 1);
    constexpr float w1r = hwin(2*s1), w1i = hwin(2*s1 + 1);
    float2 a = bp2[s0];
    float2 b = bp2[s1];
    float tr = MULC(b.x, w1r);
    float ti = MULC(b.y, w1i);
    if constexpr (w0r == 0.0f){                   // only s0 == 0 (window zero at m=0)
      Ar[2*M]     = tr;
      Ar[2*M + 1] = MULC(b.x, -w1r);              // -tr, imm-form, no neg temp
    } else {
      Ar[2*M]     = __fmaf_rn(a.x, w0r,  tr);
      Ar[2*M + 1] = __fmaf_rn(a.x, w0r, -tr);
    }
    Ai[2*M]     = __fmaf_rn(a.y, w0i,  ti);
    Ai[2*M + 1] = __fmaf_rn(a.y, w0i, -ti);
    Fused0<M + 1>::run(Ar, Ai, bp2);
  }
};
template<> struct Fused0<32>{ static DEV void run(float*, float*, const float2*){} };

// ---------------- radix-2 stage 1 (all twiddles trivial: 1 and -i) ----------------
template<int M> struct Stage1 {
  static DEV void run(float* Ar, float* Ai){
    constexpr int j  = M & 1;
    constexpr int i0 = ((M >> 1) << 2) + j;
    constexpr int i1 = i0 + 2;
    float br_ = Ar[i1], bi_ = Ai[i1];
    float ar_ = Ar[i0], ai_ = Ai[i0];
    if constexpr (j == 0){
      Ar[i0] = ADDI(ar_, br_); Ai[i0] = ADDI(ai_, bi_);
      Ar[i1] = SUBI(ar_, br_); Ai[i1] = SUBI(ai_, bi_);
    } else {                                      // w = -i: t = (bi, -br)
      Ar[i0] = ADDI(ar_, bi_); Ai[i0] = SUBI(ai_, br_);
      Ar[i1] = SUBI(ar_, bi_); Ai[i1] = ADDI(ai_, br_);
    }
    Stage1<M + 1>::run(Ar, Ai);
  }
};
template<> struct Stage1<32>{ static DEV void run(float*, float*){} };

// ---------------- radix-4 dragonfly: fuses radix-2 stages 2 and 3 ----------------
template<int S, int G> struct R4Loop {
  static DEV void run(float* Ar, float* Ai){
    constexpr int h  = 1 << S;
    constexpr int j  = G & (h - 1);
    constexpr int i0 = ((G >> S) << (S + 2)) + j;
    constexpr double ang = kPI * (double)j / (double)(2 * h);
    constexpr float c1 = (float)ccos(2.0 * ang), s1 = (float)csin(2.0 * ang);
    constexpr float c2 = (float)ccos(ang),        s2 = (float)csin(ang);
    constexpr float c3 = (float)ccos(3.0 * ang),  s3 = (float)csin(3.0 * ang);

    float x0r = Ar[i0],       x0i = Ai[i0];
    float x1r = Ar[i0 + h],   x1i = Ai[i0 + h];
    float x2r = Ar[i0 + 2*h], x2i = Ai[i0 + 2*h];
    float x3r = Ar[i0 + 3*h], x3i = Ai[i0 + 3*h];

    float r0r, r0i, r1r, r1i, u1r, u1i, u3r, u3i;
    if constexpr (j == 0){
      u1r = x2r; u1i = x2i; u3r = x3r; u3i = x3i;
      r0r = ADDI(x0r, x1r); r0i = ADDI(x0i, x1i);
      r1r = SUBI(x0r, x1r); r1i = SUBI(x0i, x1i);
    } else {
      u1r = __fmaf_rn(c2, x2r,  MULC(x2i, s2));
      u1i = __fmaf_rn(c2, x2i, -MULC(x2r, s2));
      u3r = __fmaf_rn(c3, x3r,  MULC(x3i, s3));
      u3i = __fmaf_rn(c3, x3i, -MULC(x3r, s3));
      if constexpr (2*j == h){                    // w^2 = -i: u2 = (x1i, -x1r)
        r0r = ADDI(x0r, x1i); r0i = SUBI(x0i, x1r);
        r1r = SUBI(x0r, x1i); r1i = ADDI(x0i, x1r);
      } else {
        float u2r = __fmaf_rn(c1, x1r,  MULC(x1i, s1));
        float u2i = __fmaf_rn(c1, x1i, -MULC(x1r, s1));
        r0r = ADDI(x0r, u2r); r0i = ADDI(x0i, u2i);
        r1r = SUBI(x0r, u2r); r1i = SUBI(x0i, u2i);
      }
    }
    float pr = ADDI(u1r, u3r), pi = ADDI(u1i, u3i);
    float qr = SUBI(u1r, u3r), qi = SUBI(u1i, u3i);

    Ar[i0]       = ADDI(r0r, pr);  Ai[i0]       = ADDI(r0i, pi);
    Ar[i0 + 2*h] = SUBI(r0r, pr);  Ai[i0 + 2*h] = SUBI(r0i, pi);
    Ar[i0 + h]   = ADDI(r1r, qi);  Ai[i0 + h]   = SUBI(r1i, qr);   // r1 - i*q
    Ar[i0 + 3*h] = SUBI(r1r, qi);  Ai[i0 + 3*h] = ADDI(r1i, qr);   // r1 + i*q
    R4Loop<S, G + 1>::run(Ar, Ai);
  }
};
template<int S> struct R4Loop<S, 16>{ static DEV void run(float*, float*){} };

// ---------------- radix-2 stage 4 (h = 16) ----------------
template<int M> struct Stage4 {
  static DEV void run(float* Ar, float* Ai){
    constexpr int j  = M & 15;
    constexpr int i0 = ((M >> 4) << 5) + j;
    constexpr int i1 = i0 + 16;
    float br_ = Ar[i1], bi_ = Ai[i1];
    float ar_ = Ar[i0], ai_ = Ai[i0];
    if constexpr (j == 0){
      Ar[i0] = ADDI(ar_, br_); Ai[i0] = ADDI(ai_, bi_);
      Ar[i1] = SUBI(ar_, br_); Ai[i1] = SUBI(ai_, bi_);
    } else if constexpr (j == 8){                 // w = -i
      Ar[i0] = ADDI(ar_, bi_); Ai[i0] = SUBI(ai_, br_);
      Ar[i1] = SUBI(ar_, bi_); Ai[i1] = ADDI(ai_, br_);
    } else {
      constexpr float c = (float)ccos(kPI * (double)j / 16.0);
      constexpr float s = (float)csin(kPI * (double)j / 16.0);
      float tr = __fmaf_rn(c, br_,  MULC(bi_, s));
      float ti = __fmaf_rn(c, bi_, -MULC(br_, s));
      Ar[i0] = ADDI(ar_, tr); Ai[i0] = ADDI(ai_, ti);
      Ar[i1] = SUBI(ar_, tr); Ai[i1] = SUBI(ai_, ti);
    }
    Stage4<M + 1>::run(Ar, Ai);
  }
};
template<> struct Stage4<32>{ static DEV void run(float*, float*){} };

// ---------------- real-split + magnitude + mel scatter on explicit values ----------------
template<int K>
DEV void do_pair_v(float P, float Q, float R, float S, float* mel){
  float zer = ADDI(P, R), zei = SUBI(Q, S);
  float zor = ADDI(Q, S), zoi = SUBI(R, P);
  constexpr float c = (float)ccos(kPI * (double)K / 64.0);
  constexpr float s = (float)csin(kPI * (double)K / 64.0);
  float A  = __fmaf_rn(c, zor,  MULC(zoi, s));
  float Bv = __fmaf_rn(c, zoi, -MULC(zor, s));
  scatter<K>(mel, magf(ADDI(zer, A), ADDI(zei, Bv)));
  if constexpr (bin_used(64 - K)){
    scatter<64 - K>(mel, magf(SUBI(zer, A), SUBI(Bv, zei)));
  }
}

// ---------------- fused stage-5 + real-split (R7-proven) ----------------
template<int R> struct Final {
  static DEV void run(float* Ar, float* Ai, float* mel){
    constexpr float c = (float)ccos(kPI * (double)R / 32.0);
    constexpr float s = (float)csin(kPI * (double)R / 32.0);
    float ar = Ar[R], ai = Ai[R], br = Ar[R+32], bi = Ai[R+32];
    float tr = __fmaf_rn(c, br,  MULC(bi, s));
    float ti = __fmaf_rn(c, bi, -MULC(br, s));
    float zRr  = ADDI(ar, tr), zRi  = ADDI(ai, ti);    // Z[R]
    float zRpr = SUBI(ar, tr), zRpi = SUBI(ai, ti);    // Z[R+32]
    float a2r = Ar[32-R], a2i = Ai[32-R], b2r = Ar[64-R], b2i = Ai[64-R];
    float t2r = __fmaf_rn(-c, b2r,  MULC(b2i, s));
    float t2i = __fmaf_rn(-c, b2i, -MULC(b2r, s));
    float zSr  = ADDI(a2r, t2r), zSi  = ADDI(a2i, t2i); // Z[32-R]
    float zSpr = SUBI(a2r, t2r), zSpi = SUBI(a2i, t2i); // Z[64-R]
    do_pair_v<R>     (zRr, zRi, zSpr, zSpi, mel);  // pair R: Z[R], Z[64-R]
    do_pair_v<32 - R>(zSr, zSi, zRpr, zRpi, mel);  // pair 32-R: Z[32-R], Z[32+R]
    Final<R + 1>::run(Ar, Ai, mel);
  }
};
template<> struct Final<16> {
  static DEV void run(float* Ar, float* Ai, float* mel){
    float ar = Ar[16], ai = Ai[16], br = Ar[48], bi = Ai[48];
    // w = -i: Z[16] = (ar+bi, ai-br), Z[48] = (ar-bi, ai+br)
    do_pair_v<16>(ADDI(ar, bi), SUBI(ai, br), SUBI(ar, bi), ADDI(ai, br), mel);
  }
};

// ---------------- store mel row to SMEM (untouched bins -> literal 0) ----------------
template<int J> struct StoreLoop {
  static DEV void run(float* dst, const float* mel){
    if constexpr (mel_used(J)) dst[J] = mel[J];
    else dst[J] = 0.0f;
    StoreLoop<J + 1>::run(dst, mel);
  }
};
template<> struct StoreLoop<80>{ static DEV void run(float*, const float*){} };

// ---------------- kernel ----------------
static constexpr int TPB = 128;       // one thread = one frame
static constexpr int NCOL = 81;       // 1 raw sample + 80 mel

__global__ void __launch_bounds__(TPB, 4)
mel_kernel(const float* __restrict__ x, float* __restrict__ out){
  __shared__ __align__(8) float sxe[256];         // x[t0 + i]
  __shared__ __align__(8) float sxo[256];         // x[t0 + 1 + i]  (shifted copy)
  __shared__ __align__(16) float sout[TPB * NCOL];

  const int tid = threadIdx.x;
  const int t0  = blockIdx.x * TPB;
  const float* xrow = x + (size_t)blockIdx.y * 16384;

  #pragma unroll
  for (int i = tid; i < 256; i += TPB){
    int t = t0 + i;
    sxe[i] = (t < 16384) ? xrow[t] : 0.0f;
    int t2 = t + 1;
    sxo[i] = (t2 < 16384) ? xrow[t2] : 0.0f;
  }
  __syncthreads();

  // Aligned float2 base: bp2[s] = (x[t0+tid+2s], x[t0+tid+2s+1]) for either tid parity.
  const float2* bp2 = (tid & 1) ? (const float2*)(sxo + (tid - 1))
                                : (const float2*)(sxe + tid);

  float Ar[64], Ai[64], mel[80];
  Fused0<0>::run(Ar, Ai, bp2);                    // window + bitrev load (LDS.64) + stage 0
  Stage1<0>::run(Ar, Ai);                         // stage 1 (trivial twiddles)
  R4Loop<2, 0>::run(Ar, Ai);                      // stages 2+3 fused radix-4
  Stage4<0>::run(Ar, Ai);                         // stage 4 radix-2
  // r = 0 of stage 5: Z[32] = pos0 - pos32 (w = 1); bin 0 excluded by mel matrix.
  scatter<32>(mel, magf(SUBI(Ar[0], Ar[32]), SUBI(Ai[0], Ai[32])));
  Final<1>::run(Ar, Ai, mel);                     // fused stage-5 + realsplit + mag + mel

  // stage 81-float output row in SMEM (stride 81 -> bank-conflict-free)
  float* row = sout + tid * NCOL;
  row[0] = sxe[tid];
  StoreLoop<0>::run(row + 1, mel);
  __syncthreads();

  // Bulk async 1D store SMEM -> GMEM (contiguous 41472 B, 16B-aligned both sides).
  if (tid == 0){
    uint32_t sa;
    asm("{ .reg .u64 t; cvta.to.shared.u64 t, %1; cvt.u32.u64 %0, t; }"
        : "=r"(sa) : "l"(sout));
    float* gdst = out + ((size_t)blockIdx.y * 16384 + (size_t)t0) * NCOL;
    asm volatile("fence.proxy.async.shared::cta;" ::: "memory");
    asm volatile("cp.async.bulk.global.shared::cta.bulk_group [%0], [%1], %2;"
                 :: "l"(gdst), "r"(sa), "r"((uint32_t)(TPB * NCOL * 4)) : "memory");
    asm volatile("cp.async.bulk.commit_group;" ::: "memory");
    asm volatile("cp.async.bulk.wait_group 0;" ::: "memory");
  }
}

extern "C" void kernel_launch(void* const* d_in, const int* in_sizes, int n_in,
                              void* d_out, int out_size){
  (void)in_sizes; (void)n_in; (void)out_size;
  const float* x = (const float*)d_in[0];
  float* out = (float*)d_out;
  dim3 grid(16384 / TPB, 16);
  mel_kernel<<<grid, TPB>>>(x, out);
}

// round 15
// speedup vs baseline: 1.5981x; 1.0467x over previous
#include <cuda_runtime.h>
#include <cstdint>
#include <cstddef>

#define DEV __device__ __forceinline__
#define HD __host__ __device__

typedef unsigned long long u64;

static constexpr double kPI = 3.14159265358979323846;

// ---------------- constexpr math (compile-time tables) ----------------
HD constexpr double creduce(double x){
  while (x >  kPI) x -= 2.0 * kPI;
  while (x < -kPI) x += 2.0 * kPI;
  return x;
}
HD constexpr double csin(double x){
  x = creduce(x);
  double t = x, s = x, x2 = x * x;
  for (int i = 1; i < 26; ++i){ t *= -x2 / (double)((2*i) * (2*i + 1)); s += t; }
  return s;
}
HD constexpr double ccos(double x){
  x = creduce(x);
  double t = 1.0, s = 1.0, x2 = x * x;
  for (int i = 1; i < 26; ++i){ t *= -x2 / (double)((2*i - 1) * (2*i)); s += t; }
  return s;
}
HD constexpr double clog(double x){
  double r = x, k = 0.0;
  while (r > 1.25) { r *= 0.5; k += 1.0; }
  while (r < 0.75) { r *= 2.0; k -= 1.0; }
  double z = (r - 1.0) / (r + 1.0), z2 = z * z, term = z, s = z;
  for (int i = 1; i < 60; ++i){ term *= z2; s += term / (double)(2*i + 1); }
  return 2.0 * s + k * 0.69314718055994530942;
}

// ---------------- mel filterbank, 2-sparse per spectral bin ----------------
HD constexpr double hz2mel(double f){ return 1127.0 * clog(1.0 + f / 700.0); }
HD constexpr double mel_lo(){ return hz2mel(80.0); }
HD constexpr double mel_step(){ return (hz2mel(7600.0) - hz2mel(80.0)) / 81.0; }
HD constexpr double bin_mel(int k){ return hz2mel(8000.0 * (double)k / 64.0); }

struct MelEnt { int ja; int jb; float wa; float wb; };

HD constexpr MelEnt mel_ent(int k){
  MelEnt e{-1, -1, 0.0f, 0.0f};
  double u = (bin_mel(k) - mel_lo()) / mel_step();
  if (u <= 0.0 || u >= 81.0) return e;
  int i = (int)u;
  double scale = (k == 32 || k == 64) ? 2.0 : 1.0;
  double wu = ((double)(i + 1) - u) * scale;
  double wl = (u - (double)i) * scale;
  if (i - 1 >= 0 && i - 1 <= 79){ e.ja = i - 1; e.wa = (float)wu; }
  if (i <= 79){ e.jb = i; e.wb = (float)wl; }
  return e;
}
HD constexpr bool bin_used(int k){
  MelEnt e = mel_ent(k);
  return e.ja >= 0 || e.jb >= 0;
}

// Emission order = exact runtime order of the fused final loop (R7-proven):
// idx 0: bin 32; idx 1..60: r=1..15, sub order (r, 64-r, 32-r, 32+r); idx 61,62: bins 16, 48.
HD constexpr int emit_bin(int idx){
  if (idx == 0) return 32;
  if (idx <= 60){
    int r = (idx - 1) / 4 + 1, sub = (idx - 1) % 4;
    return sub == 0 ? r : sub == 1 ? 64 - r : sub == 2 ? 32 - r : 32 + r;
  }
  return idx == 61 ? 16 : 48;
}
HD constexpr int targ(int bin, int slot){
  MelEnt e = mel_ent(bin);
  return slot ? e.jb : e.ja;
}
HD constexpr int emit_pos(int bin){
  for (int idx = 0; idx < 63; ++idx) if (emit_bin(idx) == bin) return idx;
  return -1;
}
HD constexpr bool is_first_touch(int bin, int slot){
  int j = targ(bin, slot);
  if (j < 0) return false;
  int pos = emit_pos(bin);
  for (int idx = 0; idx < pos; ++idx){
    int b2 = emit_bin(idx);
    if (targ(b2, 0) == j || targ(b2, 1) == j) return false;
  }
  if (slot == 1 && targ(bin, 0) == j) return false;
  return true;
}
HD constexpr bool mel_used(int j){
  for (int idx = 0; idx < 63; ++idx){
    int b2 = emit_bin(idx);
    if (targ(b2, 0) == j || targ(b2, 1) == j) return true;
  }
  return false;
}
HD constexpr int bitrev6(int n){
  int r = 0;
  for (int b = 0; b < 6; ++b) r |= ((n >> b) & 1) << (5 - b);
  return r;
}

// pre-halved Hann window: 0.5 * (0.5 - 0.5*cos(2*pi*m/128))
HD constexpr float hwin(int m){
  return (float)(0.5 * (0.5 - 0.5 * ccos(2.0 * kPI * (double)m / 128.0)));
}

// ---------------- packed f32x2 primitives (FFMA2 path, PTX-only) ----------------
struct PC { u64 n1, pm, mp; };   // (-1,-1), (1,-1), (-1,1) lane multipliers

DEV u64 PKF(float lo, float hi){
  u64 r;
  asm("mov.b64 %0, {%1, %2};" : "=l"(r) : "r"(__float_as_int(lo)), "r"(__float_as_int(hi)));
  return r;
}
DEV void UPKF(u64 v, float& lo, float& hi){
  int l, h;
  asm("mov.b64 {%0, %1}, %2;" : "=r"(l), "=r"(h) : "l"(v));
  lo = __int_as_float(l); hi = __int_as_float(h);
}
DEV u64 SWP(u64 v){
  int l, h;
  asm("mov.b64 {%0, %1}, %2;" : "=r"(l), "=r"(h) : "l"(v));
  u64 r;
  asm("mov.b64 %0, {%1, %2};" : "=l"(r) : "r"(h), "r"(l));
  return r;
}
DEV u64 ADD2(u64 a, u64 b){
  u64 r;
  asm("add.rn.f32x2 %0, %1, %2;" : "=l"(r) : "l"(a), "l"(b));
  return r;
}
DEV u64 FMA2(u64 a, u64 b, u64 c){
  u64 r;
  asm("fma.rn.f32x2 %0, %1, %2, %3;" : "=l"(r) : "l"(a), "l"(b), "l"(c));
  return r;
}
// a - b (per lane, exact: b*(-1) exact + single rounding)
DEV u64 SUB2(u64 a, u64 b, u64 n1){ return FMA2(b, n1, a); }

// ---------------- magnitude: MUFU.SQRT (p2 >= 0 always; sqrt.approx(0/denorm) = 0) ----
DEV float magf(float re, float im){
  float p2 = fmaf(re, re, im * im);
  float m;
  asm("sqrt.approx.f32 %0, %1;" : "=f"(m) : "f"(p2));
  return m;
}

// ---------------- mel scatter (static register indices, proven) ----------------
template<int BIN>
DEV void scatter(float* mel, float mag){
  constexpr MelEnt e = mel_ent(BIN);
  if constexpr (e.ja >= 0){
    if constexpr (is_first_touch(BIN, 0)) mel[e.ja] = e.wa * mag;
    else mel[e.ja] = fmaf(e.wa, mag, mel[e.ja]);
  }
  if constexpr (e.jb >= 0){
    if constexpr (is_first_touch(BIN, 1)) mel[e.jb] = e.wb * mag;
    else mel[e.jb] = fmaf(e.wb, mag, mel[e.jb]);
  }
}

// ---------------- fused window + bit-reversed load + stage-0, paired LDS.64 ----------
// bp2[s] aliases (x[t0+tid+2s], x[t0+tid+2s+1]); result stored packed (re,im).
template<int M> struct Fused0 {
  static DEV void run(u64* A, const float2* bp2){
    constexpr int s0 = bitrev6(2*M);
    constexpr int s1 = bitrev6(2*M + 1);          // = s0 + 32
    constexpr float w0r = hwin(2*s0), w0i = hwin(2*s0 + 1);
    constexpr float w1r = hwin(2*s1), w1i = hwin(2*s1 + 1);
    float2 a = bp2[s0];
    float2 b = bp2[s1];
    float tr = b.x * w1r;
    float ti = b.y * w1i;
    float e0i = fmaf(a.y, w0i,  ti);
    float e1i = fmaf(a.y, w0i, -ti);
    if constexpr (w0r == 0.0f){                   // only s0 == 0 (window zero at m=0)
      A[2*M]     = PKF(tr, e0i);
      A[2*M + 1] = PKF(b.x * (-w1r), e1i);
    } else {
      A[2*M]     = PKF(fmaf(a.x, w0r,  tr), e0i);
      A[2*M + 1] = PKF(fmaf(a.x, w0r, -tr), e1i);
    }
    Fused0<M + 1>::run(A, bp2);
  }
};
template<> struct Fused0<32>{ static DEV void run(u64*, const float2*){} };

// ---------------- radix-2 stage 1 (twiddles 1 and -i), packed ----------------
template<int M> struct Stage1 {
  static DEV void run(u64* A, const PC& pc){
    constexpr int j  = M & 1;
    constexpr int i0 = ((M >> 1) << 2) + j;
    constexpr int i1 = i0 + 2;
    u64 a = A[i0], b = A[i1];
    if constexpr (j == 0){
      A[i0] = ADD2(a, b);
      A[i1] = SUB2(a, b, pc.n1);
    } else {                                      // w = -i: t = (bi, -br)
      u64 sb = SWP(b);
      A[i0] = FMA2(sb, pc.pm, a);                 // (ar+bi, ai-br)
      A[i1] = FMA2(sb, pc.mp, a);                 // (ar-bi, ai+br)
    }
    Stage1<M + 1>::run(A, pc);
  }
};
template<> struct Stage1<32>{ static DEV void run(u64*, const PC&){} };

// ---------------- radix-4 dragonfly (stages 2+3), packed combines ----------------
template<int S, int G> struct R4Loop {
  static DEV void run(u64* A, const PC& pc){
    constexpr int h  = 1 << S;
    constexpr int j  = G & (h - 1);
    constexpr int i0 = ((G >> S) << (S + 2)) + j;
    constexpr double ang = kPI * (double)j / (double)(2 * h);
    constexpr float c1 = (float)ccos(2.0 * ang), s1 = (float)csin(2.0 * ang);
    constexpr float c2 = (float)ccos(ang),        s2 = (float)csin(ang);
    constexpr float c3 = (float)ccos(3.0 * ang),  s3 = (float)csin(3.0 * ang);

    u64 x0 = A[i0], x1 = A[i0 + h], x2 = A[i0 + 2*h], x3 = A[i0 + 3*h];
    u64 r0, r1, u1, u3;
    if constexpr (j == 0){
      u1 = x2; u3 = x3;
      r0 = ADD2(x0, x1);
      r1 = SUB2(x0, x1, pc.n1);
    } else {
      float x2r, x2i, x3r, x3i;
      UPKF(x2, x2r, x2i); UPKF(x3, x3r, x3i);
      u1 = PKF(fmaf(c2, x2r,  s2 * x2i), fmaf(c2, x2i, -(s2 * x2r)));
      u3 = PKF(fmaf(c3, x3r,  s3 * x3i), fmaf(c3, x3i, -(s3 * x3r)));
      if constexpr (2*j == h){                    // w^2 = -i
        u64 sx1 = SWP(x1);
        r0 = FMA2(sx1, pc.pm, x0);
        r1 = FMA2(sx1, pc.mp, x0);
      } else {
        float x1r, x1i; UPKF(x1, x1r, x1i);
        u64 u2 = PKF(fmaf(c1, x1r,  s1 * x1i), fmaf(c1, x1i, -(s1 * x1r)));
        r0 = ADD2(x0, u2);
        r1 = SUB2(x0, u2, pc.n1);
      }
    }
    u64 p = ADD2(u1, u3);
    u64 q = SUB2(u1, u3, pc.n1);
    A[i0]         = ADD2(r0, p);
    A[i0 + 2*h]   = SUB2(r0, p, pc.n1);
    u64 sq = SWP(q);
    A[i0 + h]     = FMA2(sq, pc.pm, r1);          // (r1r+qi, r1i-qr) = r1 - i*q
    A[i0 + 3*h]   = FMA2(sq, pc.mp, r1);          // (r1r-qi, r1i+qr) = r1 + i*q
    R4Loop<S, G + 1>::run(A, pc);
  }
};
template<int S> struct R4Loop<S, 16>{ static DEV void run(u64*, const PC&){} };

// ---------------- radix-2 stage 4 (h = 16), packed combines ----------------
template<int M> struct Stage4 {
  static DEV void run(u64* A, const PC& pc){
    constexpr int j  = M & 15;
    constexpr int i0 = ((M >> 4) << 5) + j;
    constexpr int i1 = i0 + 16;
    u64 a = A[i0], b = A[i1];
    if constexpr (j == 0){
      A[i0] = ADD2(a, b);
      A[i1] = SUB2(a, b, pc.n1);
    } else if constexpr (j == 8){                 // w = -i
      u64 sb = SWP(b);
      A[i0] = FMA2(sb, pc.pm, a);
      A[i1] = FMA2(sb, pc.mp, a);
    } else {
      constexpr float c = (float)ccos(kPI * (double)j / 16.0);
      constexpr float s = (float)csin(kPI * (double)j / 16.0);
      float br, bi; UPKF(b, br, bi);
      u64 t = PKF(fmaf(c, br,  s * bi), fmaf(c, bi, -(s * br)));
      A[i0] = ADD2(a, t);
      A[i1] = SUB2(a, t, pc.n1);
    }
    Stage4<M + 1>::run(A, pc);
  }
};
template<> struct Stage4<32>{ static DEV void run(u64*, const PC&){} };

// ---------------- real-split + magnitude + mel scatter on packed Z values --------
// Z1 = Z[K] = (P,Q); Z2 = Z[64-K] = (R,S)
template<int K>
DEV void do_pair_v(u64 Z1, u64 Z2, float* mel, const PC& pc){
  u64 ze = FMA2(Z2, pc.pm, Z1);                   // (P+R, Q-S) = (zer, zei)
  float P, Q, R, S;
  UPKF(Z1, P, Q); UPKF(Z2, R, S);
  float zor = Q + S;
  float zoi = R - P;
  constexpr float c = (float)ccos(kPI * (double)K / 64.0);
  constexpr float s = (float)csin(kPI * (double)K / 64.0);
  float A_ = fmaf(c, zor,  s * zoi);
  float Bv = fmaf(c, zoi, -(s * zor));
  u64 m1 = ADD2(ze, PKF(A_, Bv));                 // (zer+A, zei+Bv)
  float m1r, m1i; UPKF(m1, m1r, m1i);
  scatter<K>(mel, magf(m1r, m1i));
  if constexpr (bin_used(64 - K)){
    float zer, zei; UPKF(ze, zer, zei);
    scatter<64 - K>(mel, magf(zer - A_, Bv - zei));
  }
}

// ---------------- fused stage-5 + real-split, packed (R7-proven math) -------------
template<int R> struct Final {
  static DEV void run(u64* A, float* mel, const PC& pc){
    constexpr float c = (float)ccos(kPI * (double)R / 32.0);
    constexpr float s = (float)csin(kPI * (double)R / 32.0);
    u64 a = A[R], b = A[R + 32];
    float br, bi; UPKF(b, br, bi);
    u64 t = PKF(fmaf(c, br,  s * bi), fmaf(c, bi, -(s * br)));
    u64 zR  = ADD2(a, t);                         // Z[R]
    u64 zRp = SUB2(a, t, pc.n1);                  // Z[R+32]
    u64 a2 = A[32 - R], b2 = A[64 - R];
    float b2r, b2i; UPKF(b2, b2r, b2i);
    u64 t2 = PKF(fmaf(-c, b2r,  s * b2i), fmaf(-c, b2i, -(s * b2r)));
    u64 zS  = ADD2(a2, t2);                       // Z[32-R]
    u64 zSp = SUB2(a2, t2, pc.n1);                // Z[64-R]
    do_pair_v<R>     (zR, zSp, mel, pc);          // pair R: Z[R], Z[64-R]
    do_pair_v<32 - R>(zS, zRp, mel, pc);          // pair 32-R: Z[32-R], Z[32+R]
    Final<R + 1>::run(A, mel, pc);
  }
};
template<> struct Final<16> {
  static DEV void run(u64* A, float* mel, const PC& pc){
    u64 a = A[16], b = A[48];
    u64 sb = SWP(b);
    u64 z16 = FMA2(sb, pc.pm, a);                 // (ar+bi, ai-br) = Z[16]
    u64 z48 = FMA2(sb, pc.mp, a);                 // (ar-bi, ai+br) = Z[48]
    do_pair_v<16>(z16, z48, mel, pc);
  }
};

// ---------------- store mel row to SMEM (untouched bins -> literal 0) ----------------
template<int J> struct StoreLoop {
  static DEV void run(float* dst, const float* mel){
    if constexpr (mel_used(J)) dst[J] = mel[J];
    else dst[J] = 0.0f;
    StoreLoop<J + 1>::run(dst, mel);
  }
};
template<> struct StoreLoop<80>{ static DEV void run(float*, const float*){} };

// ---------------- kernel ----------------
static constexpr int TPB = 128;       // one thread = one frame
static constexpr int NCOL = 81;       // 1 raw sample + 80 mel

__global__ void __launch_bounds__(TPB, 4)
mel_kernel(const float* __restrict__ x, float* __restrict__ out){
  __shared__ __align__(8) float sxe[256];         // x[t0 + i]
  __shared__ __align__(8) float sxo[256];         // x[t0 + 1 + i]  (shifted copy)
  __shared__ __align__(16) float sout[TPB * NCOL];

  const int tid = threadIdx.x;
  const int t0  = blockIdx.x * TPB;
  const float* xrow = x + (size_t)blockIdx.y * 16384;

  #pragma unroll
  for (int i = tid; i < 256; i += TPB){
    int t = t0 + i;
    sxe[i] = (t < 16384) ? xrow[t] : 0.0f;
    int t2 = t + 1;
    sxo[i] = (t2 < 16384) ? xrow[t2] : 0.0f;
  }
  __syncthreads();

  // lane-mask constants for packed ops (materialized once)
  PC pc;
  asm("mov.b64 %0, 0xBF800000BF800000;" : "=l"(pc.n1));  // (-1,-1)
  asm("mov.b64 %0, 0xBF8000003F800000;" : "=l"(pc.pm));  // lo=+1, hi=-1
  asm("mov.b64 %0, 0x3F800000BF800000;" : "=l"(pc.mp));  // lo=-1, hi=+1

  // Aligned float2 base: bp2[s] = (x[t0+tid+2s], x[t0+tid+2s+1]) for either tid parity.
  const float2* bp2 = (tid & 1) ? (const float2*)(sxo + (tid - 1))
                                : (const float2*)(sxe + tid);

  u64 A[64];
  float mel[80];
  Fused0<0>::run(A, bp2);                         // window + bitrev load (LDS.64) + stage 0
  Stage1<0>::run(A, pc);                          // stage 1 (trivial twiddles, packed)
  R4Loop<2, 0>::run(A, pc);                       // stages 2+3 fused radix-4, packed combines
  Stage4<0>::run(A, pc);                          // stage 4 radix-2, packed combines
  // r = 0 of stage 5: Z[32] = pos0 - pos32 (w = 1); bin 0 excluded by mel matrix.
  {
    u64 zm = SUB2(A[0], A[32], pc.n1);
    float zr, zi; UPKF(zm, zr, zi);
    scatter<32>(mel, magf(zr, zi));
  }
  Final<1>::run(A, mel, pc);                      // fused stage-5 + realsplit + mag + mel

  // stage 81-float output row in SMEM (stride 81 -> bank-conflict-free)
  float* row = sout + tid * NCOL;
  row[0] = sxe[tid];
  StoreLoop<0>::run(row + 1, mel);
  __syncthreads();

  // Bulk async 1D store SMEM -> GMEM (contiguous 41472 B, 16B-aligned both sides).
  if (tid == 0){
    uint32_t sa;
    asm("{ .reg .u64 t; cvta.to.shared.u64 t, %1; cvt.u32.u64 %0, t; }"
        : "=r"(sa) : "l"(sout));
    float* gdst = out + ((size_t)blockIdx.y * 16384 + (size_t)t0) * NCOL;
    asm volatile("fence.proxy.async.shared::cta;" ::: "memory");
    asm volatile("cp.async.bulk.global.shared::cta.bulk_group [%0], [%1], %2;"
                 :: "l"(gdst), "r"(sa), "r"((uint32_t)(TPB * NCOL * 4)) : "memory");
    asm volatile("cp.async.bulk.commit_group;" ::: "memory");
    asm volatile("cp.async.bulk.wait_group 0;" ::: "memory");
  }
}

extern "C" void kernel_launch(void* const* d_in, const int* in_sizes, int n_in,
                              void* d_out, int out_size){
  (void)in_sizes; (void)n_in; (void)out_size;
  const float* x = (const float*)d_in[0];
  float* out = (float*)d_out;
  dim3 grid(16384 / TPB, 16);
  mel_kernel<<<grid, TPB>>>(x, out);
}

// round 16
// speedup vs baseline: 1.6000x; 1.0012x over previous
#include <cuda_runtime.h>
#include <cstdint>
#include <cstddef>

#define DEV __device__ __forceinline__
#define HD __host__ __device__

typedef unsigned long long u64;

static constexpr double kPI = 3.14159265358979323846;

// ---------------- constexpr math (compile-time tables) ----------------
HD constexpr double creduce(double x){
  while (x >  kPI) x -= 2.0 * kPI;
  while (x < -kPI) x += 2.0 * kPI;
  return x;
}
HD constexpr double csin(double x){
  x = creduce(x);
  double t = x, s = x, x2 = x * x;
  for (int i = 1; i < 26; ++i){ t *= -x2 / (double)((2*i) * (2*i + 1)); s += t; }
  return s;
}
HD constexpr double ccos(double x){
  x = creduce(x);
  double t = 1.0, s = 1.0, x2 = x * x;
  for (int i = 1; i < 26; ++i){ t *= -x2 / (double)((2*i - 1) * (2*i)); s += t; }
  return s;
}
HD constexpr double clog(double x){
  double r = x, k = 0.0;
  while (r > 1.25) { r *= 0.5; k += 1.0; }
  while (r < 0.75) { r *= 2.0; k -= 1.0; }
  double z = (r - 1.0) / (r + 1.0), z2 = z * z, term = z, s = z;
  for (int i = 1; i < 60; ++i){ term *= z2; s += term / (double)(2*i + 1); }
  return 2.0 * s + k * 0.69314718055994530942;
}

// ---------------- mel filterbank, 2-sparse per spectral bin ----------------
HD constexpr double hz2mel(double f){ return 1127.0 * clog(1.0 + f / 700.0); }
HD constexpr double mel_lo(){ return hz2mel(80.0); }
HD constexpr double mel_step(){ return (hz2mel(7600.0) - hz2mel(80.0)) / 81.0; }
HD constexpr double bin_mel(int k){ return hz2mel(8000.0 * (double)k / 64.0); }

struct MelEnt { int ja; int jb; float wa; float wb; };

HD constexpr MelEnt mel_ent(int k){
  MelEnt e{-1, -1, 0.0f, 0.0f};
  double u = (bin_mel(k) - mel_lo()) / mel_step();
  if (u <= 0.0 || u >= 81.0) return e;
  int i = (int)u;
  double scale = (k == 32 || k == 64) ? 2.0 : 1.0;
  double wu = ((double)(i + 1) - u) * scale;
  double wl = (u - (double)i) * scale;
  if (i - 1 >= 0 && i - 1 <= 79){ e.ja = i - 1; e.wa = (float)wu; }
  if (i <= 79){ e.jb = i; e.wb = (float)wl; }
  return e;
}
HD constexpr bool bin_used(int k){
  MelEnt e = mel_ent(k);
  return e.ja >= 0 || e.jb >= 0;
}

// Emission order = exact runtime order of the fused final loop (R7-proven):
// idx 0: bin 32; idx 1..60: r=1..15, sub order (r, 64-r, 32-r, 32+r); idx 61,62: bins 16, 48.
HD constexpr int emit_bin(int idx){
  if (idx == 0) return 32;
  if (idx <= 60){
    int r = (idx - 1) / 4 + 1, sub = (idx - 1) % 4;
    return sub == 0 ? r : sub == 1 ? 64 - r : sub == 2 ? 32 - r : 32 + r;
  }
  return idx == 61 ? 16 : 48;
}
HD constexpr int targ(int bin, int slot){
  MelEnt e = mel_ent(bin);
  return slot ? e.jb : e.ja;
}
HD constexpr int emit_pos(int bin){
  for (int idx = 0; idx < 63; ++idx) if (emit_bin(idx) == bin) return idx;
  return -1;
}
HD constexpr bool is_first_touch(int bin, int slot){
  int j = targ(bin, slot);
  if (j < 0) return false;
  int pos = emit_pos(bin);
  for (int idx = 0; idx < pos; ++idx){
    int b2 = emit_bin(idx);
    if (targ(b2, 0) == j || targ(b2, 1) == j) return false;
  }
  if (slot == 1 && targ(bin, 0) == j) return false;
  return true;
}
HD constexpr bool mel_used(int j){
  for (int idx = 0; idx < 63; ++idx){
    int b2 = emit_bin(idx);
    if (targ(b2, 0) == j || targ(b2, 1) == j) return true;
  }
  return false;
}
HD constexpr int bitrev6(int n){
  int r = 0;
  for (int b = 0; b < 6; ++b) r |= ((n >> b) & 1) << (5 - b);
  return r;
}

// pre-halved Hann window: 0.5 * (0.5 - 0.5*cos(2*pi*m/128))
HD constexpr float hwin(int m){
  return (float)(0.5 * (0.5 - 0.5 * ccos(2.0 * kPI * (double)m / 128.0)));
}

// ---------------- packed f32x2 primitives (FFMA2 path, PTX-only) ----------------
struct PC { u64 n1, pm, mp; };   // (-1,-1), (1,-1), (-1,1) lane multipliers

DEV u64 PKF(float lo, float hi){
  u64 r;
  asm("mov.b64 %0, {%1, %2};" : "=l"(r) : "r"(__float_as_int(lo)), "r"(__float_as_int(hi)));
  return r;
}
DEV void UPKF(u64 v, float& lo, float& hi){
  int l, h;
  asm("mov.b64 {%0, %1}, %2;" : "=r"(l), "=r"(h) : "l"(v));
  lo = __int_as_float(l); hi = __int_as_float(h);
}
DEV u64 SWP(u64 v){
  int l, h;
  asm("mov.b64 {%0, %1}, %2;" : "=r"(l), "=r"(h) : "l"(v));
  u64 r;
  asm("mov.b64 %0, {%1, %2};" : "=l"(r) : "r"(h), "r"(l));
  return r;
}
DEV u64 ADD2(u64 a, u64 b){
  u64 r;
  asm("add.rn.f32x2 %0, %1, %2;" : "=l"(r) : "l"(a), "l"(b));
  return r;
}
DEV u64 FMA2(u64 a, u64 b, u64 c){
  u64 r;
  asm("fma.rn.f32x2 %0, %1, %2, %3;" : "=l"(r) : "l"(a), "l"(b), "l"(c));
  return r;
}
// a - b (per lane, exact: b*(-1) exact + single rounding)
DEV u64 SUB2(u64 a, u64 b, u64 n1){ return FMA2(b, n1, a); }

// ---------------- magnitude: MUFU.SQRT (p2 >= 0 always; sqrt.approx(0/denorm) = 0) ----
DEV float magf(float re, float im){
  float p2 = fmaf(re, re, im * im);
  float m;
  asm("sqrt.approx.f32 %0, %1;" : "=f"(m) : "f"(p2));
  return m;
}

// ---------------- mel scatter (static register indices, proven) ----------------
template<int BIN>
DEV void scatter(float* mel, float mag){
  constexpr MelEnt e = mel_ent(BIN);
  if constexpr (e.ja >= 0){
    if constexpr (is_first_touch(BIN, 0)) mel[e.ja] = e.wa * mag;
    else mel[e.ja] = fmaf(e.wa, mag, mel[e.ja]);
  }
  if constexpr (e.jb >= 0){
    if constexpr (is_first_touch(BIN, 1)) mel[e.jb] = e.wb * mag;
    else mel[e.jb] = fmaf(e.wb, mag, mel[e.jb]);
  }
}

// ---------------- fused window + bit-reversed load + stage-0, paired LDS.64 ----------
// bp2[s] aliases (x[t0+tid+2s], x[t0+tid+2s+1]); result stored packed (re,im).
template<int M> struct Fused0 {
  static DEV void run(u64* A, const float2* bp2){
    constexpr int s0 = bitrev6(2*M);
    constexpr int s1 = bitrev6(2*M + 1);          // = s0 + 32
    constexpr float w0r = hwin(2*s0), w0i = hwin(2*s0 + 1);
    constexpr float w1r = hwin(2*s1), w1i = hwin(2*s1 + 1);
    float2 a = bp2[s0];
    float2 b = bp2[s1];
    float tr = b.x * w1r;
    float ti = b.y * w1i;
    float e0i = fmaf(a.y, w0i,  ti);
    float e1i = fmaf(a.y, w0i, -ti);
    if constexpr (w0r == 0.0f){                   // only s0 == 0 (window zero at m=0)
      A[2*M]     = PKF(tr, e0i);
      A[2*M + 1] = PKF(b.x * (-w1r), e1i);
    } else {
      A[2*M]     = PKF(fmaf(a.x, w0r,  tr), e0i);
      A[2*M + 1] = PKF(fmaf(a.x, w0r, -tr), e1i);
    }
    Fused0<M + 1>::run(A, bp2);
  }
};
template<> struct Fused0<32>{ static DEV void run(u64*, const float2*){} };

// ---------------- radix-2 stage 1 (twiddles 1 and -i), packed ----------------
template<int M> struct Stage1 {
  static DEV void run(u64* A, const PC& pc){
    constexpr int j  = M & 1;
    constexpr int i0 = ((M >> 1) << 2) + j;
    constexpr int i1 = i0 + 2;
    u64 a = A[i0], b = A[i1];
    if constexpr (j == 0){
      A[i0] = ADD2(a, b);
      A[i1] = SUB2(a, b, pc.n1);
    } else {                                      // w = -i: t = (bi, -br)
      u64 sb = SWP(b);
      A[i0] = FMA2(sb, pc.pm, a);                 // (ar+bi, ai-br)
      A[i1] = FMA2(sb, pc.mp, a);                 // (ar-bi, ai+br)
    }
    Stage1<M + 1>::run(A, pc);
  }
};
template<> struct Stage1<32>{ static DEV void run(u64*, const PC&){} };

// ---------------- radix-4 dragonfly (stages 2+3), packed combines ----------------
template<int S, int G> struct R4Loop {
  static DEV void run(u64* A, const PC& pc){
    constexpr int h  = 1 << S;
    constexpr int j  = G & (h - 1);
    constexpr int i0 = ((G >> S) << (S + 2)) + j;
    constexpr double ang = kPI * (double)j / (double)(2 * h);
    constexpr float c1 = (float)ccos(2.0 * ang), s1 = (float)csin(2.0 * ang);
    constexpr float c2 = (float)ccos(ang),        s2 = (float)csin(ang);
    constexpr float c3 = (float)ccos(3.0 * ang),  s3 = (float)csin(3.0 * ang);

    u64 x0 = A[i0], x1 = A[i0 + h], x2 = A[i0 + 2*h], x3 = A[i0 + 3*h];
    u64 r0, r1, u1, u3;
    if constexpr (j == 0){
      u1 = x2; u3 = x3;
      r0 = ADD2(x0, x1);
      r1 = SUB2(x0, x1, pc.n1);
    } else {
      float x2r, x2i, x3r, x3i;
      UPKF(x2, x2r, x2i); UPKF(x3, x3r, x3i);
      u1 = PKF(fmaf(c2, x2r,  s2 * x2i), fmaf(c2, x2i, -(s2 * x2r)));
      u3 = PKF(fmaf(c3, x3r,  s3 * x3i), fmaf(c3, x3i, -(s3 * x3r)));
      if constexpr (2*j == h){                    // w^2 = -i
        u64 sx1 = SWP(x1);
        r0 = FMA2(sx1, pc.pm, x0);
        r1 = FMA2(sx1, pc.mp, x0);
      } else {
        float x1r, x1i; UPKF(x1, x1r, x1i);
        u64 u2 = PKF(fmaf(c1, x1r,  s1 * x1i), fmaf(c1, x1i, -(s1 * x1r)));
        r0 = ADD2(x0, u2);
        r1 = SUB2(x0, u2, pc.n1);
      }
    }
    u64 p = ADD2(u1, u3);
    u64 q = SUB2(u1, u3, pc.n1);
    A[i0]         = ADD2(r0, p);
    A[i0 + 2*h]   = SUB2(r0, p, pc.n1);
    u64 sq = SWP(q);
    A[i0 + h]     = FMA2(sq, pc.pm, r1);          // (r1r+qi, r1i-qr) = r1 - i*q
    A[i0 + 3*h]   = FMA2(sq, pc.mp, r1);          // (r1r-qi, r1i+qr) = r1 + i*q
    R4Loop<S, G + 1>::run(A, pc);
  }
};
template<int S> struct R4Loop<S, 16>{ static DEV void run(u64*, const PC&){} };

// ---------------- radix-2 stage 4 (h = 16), packed combines ----------------
template<int M> struct Stage4 {
  static DEV void run(u64* A, const PC& pc){
    constexpr int j  = M & 15;
    constexpr int i0 = ((M >> 4) << 5) + j;
    constexpr int i1 = i0 + 16;
    u64 a = A[i0], b = A[i1];
    if constexpr (j == 0){
      A[i0] = ADD2(a, b);
      A[i1] = SUB2(a, b, pc.n1);
    } else if constexpr (j == 8){                 // w = -i
      u64 sb = SWP(b);
      A[i0] = FMA2(sb, pc.pm, a);
      A[i1] = FMA2(sb, pc.mp, a);
    } else {
      constexpr float c = (float)ccos(kPI * (double)j / 16.0);
      constexpr float s = (float)csin(kPI * (double)j / 16.0);
      float br, bi; UPKF(b, br, bi);
      u64 t = PKF(fmaf(c, br,  s * bi), fmaf(c, bi, -(s * br)));
      A[i0] = ADD2(a, t);
      A[i1] = SUB2(a, t, pc.n1);
    }
    Stage4<M + 1>::run(A, pc);
  }
};
template<> struct Stage4<32>{ static DEV void run(u64*, const PC&){} };

// ---------------- real-split + magnitude + mel scatter on explicit values (R12) -----
template<int K>
DEV void do_pair_v(float P, float Q, float R, float S, float* mel){
  float zer = P + R, zei = Q - S;
  float zor = Q + S, zoi = R - P;
  constexpr float c = (float)ccos(kPI * (double)K / 64.0);
  constexpr float s = (float)csin(kPI * (double)K / 64.0);
  float A  = fmaf(c, zor,  s * zoi);
  float Bv = fmaf(c, zoi, -(s * zor));
  scatter<K>(mel, magf(zer + A, zei + Bv));
  if constexpr (bin_used(64 - K)){
    scatter<64 - K>(mel, magf(zer - A, Bv - zei));
  }
}

// ---------------- fused stage-5 + real-split, scalar (R12-proven) ----------------
template<int R> struct Final {
  static DEV void run(float* Ar, float* Ai, float* mel){
    constexpr float c = (float)ccos(kPI * (double)R / 32.0);
    constexpr float s = (float)csin(kPI * (double)R / 32.0);
    float ar = Ar[R], ai = Ai[R], br = Ar[R+32], bi = Ai[R+32];
    float tr = fmaf(c, br,  s * bi);
    float ti = fmaf(c, bi, -(s * br));
    float zRr  = ar + tr, zRi  = ai + ti;          // Z[R]
    float zRpr = ar - tr, zRpi = ai - ti;          // Z[R+32]
    float a2r = Ar[32-R], a2i = Ai[32-R], b2r = Ar[64-R], b2i = Ai[64-R];
    float t2r = fmaf(-c, b2r,  s * b2i);
    float t2i = fmaf(-c, b2i, -(s * b2r));
    float zSr  = a2r + t2r, zSi  = a2i + t2i;      // Z[32-R]
    float zSpr = a2r - t2r, zSpi = a2i - t2i;      // Z[64-R]
    do_pair_v<R>     (zRr, zRi, zSpr, zSpi, mel);  // pair R: Z[R], Z[64-R]
    do_pair_v<32 - R>(zSr, zSi, zRpr, zRpi, mel);  // pair 32-R: Z[32-R], Z[32+R]
    Final<R + 1>::run(Ar, Ai, mel);
  }
};
template<> struct Final<16> {
  static DEV void run(float* Ar, float* Ai, float* mel){
    float ar = Ar[16], ai = Ai[16], br = Ar[48], bi = Ai[48];
    do_pair_v<16>(ar + bi, ai - br, ar - bi, ai + br, mel);   // w = -i
  }
};

// ---------------- store mel row to SMEM (untouched bins -> literal 0) ----------------
template<int J> struct StoreLoop {
  static DEV void run(float* dst, const float* mel){
    if constexpr (mel_used(J)) dst[J] = mel[J];
    else dst[J] = 0.0f;
    StoreLoop<J + 1>::run(dst, mel);
  }
};
template<> struct StoreLoop<80>{ static DEV void run(float*, const float*){} };

// ---------------- kernel ----------------
static constexpr int TPB = 128;       // one thread = one frame
static constexpr int NCOL = 81;       // 1 raw sample + 80 mel

__global__ void __launch_bounds__(TPB, 4)
mel_kernel(const float* __restrict__ x, float* __restrict__ out){
  __shared__ __align__(8) float sxe[256];         // x[t0 + i]
  __shared__ __align__(8) float sxo[256];         // x[t0 + 1 + i]  (shifted copy)
  __shared__ __align__(16) float sout[TPB * NCOL];

  const int tid = threadIdx.x;
  const int t0  = blockIdx.x * TPB;
  const float* xrow = x + (size_t)blockIdx.y * 16384;

  #pragma unroll
  for (int i = tid; i < 256; i += TPB){
    int t = t0 + i;
    sxe[i] = (t < 16384) ? xrow[t] : 0.0f;
    int t2 = t + 1;
    sxo[i] = (t2 < 16384) ? xrow[t2] : 0.0f;
  }
  __syncthreads();

  // lane-mask constants for packed ops (materialized once)
  PC pc;
  asm("mov.b64 %0, 0xBF800000BF800000;" : "=l"(pc.n1));  // (-1,-1)
  asm("mov.b64 %0, 0xBF8000003F800000;" : "=l"(pc.pm));  // lo=+1, hi=-1
  asm("mov.b64 %0, 0x3F800000BF800000;" : "=l"(pc.mp));  // lo=-1, hi=+1

  // Aligned float2 base: bp2[s] = (x[t0+tid+2s], x[t0+tid+2s+1]) for either tid parity.
  const float2* bp2 = (tid & 1) ? (const float2*)(sxo + (tid - 1))
                                : (const float2*)(sxe + tid);

  u64 A[64];
  Fused0<0>::run(A, bp2);                         // window + bitrev load (LDS.64) + stage 0
  Stage1<0>::run(A, pc);                          // stage 1 (trivial twiddles, packed)
  R4Loop<2, 0>::run(A, pc);                       // stages 2+3 fused radix-4, packed combines
  Stage4<0>::run(A, pc);                          // stage 4 radix-2, packed combines

  // ---- unpack bridge: packed state -> scalar arrays (register renaming only) ----
  float Ar[64], Ai[64], mel[80];
  #pragma unroll
  for (int k = 0; k < 64; ++k) UPKF(A[k], Ar[k], Ai[k]);

  // r = 0 of stage 5: Z[32] = pos0 - pos32 (w = 1); bin 0 excluded by mel matrix.
  scatter<32>(mel, magf(Ar[0] - Ar[32], Ai[0] - Ai[32]));
  Final<1>::run(Ar, Ai, mel);                     // fused stage-5 + realsplit + mag + mel (scalar)

  // stage 81-float output row in SMEM (stride 81 -> bank-conflict-free)
  float* row = sout + tid * NCOL;
  row[0] = sxe[tid];
  StoreLoop<0>::run(row + 1, mel);
  __syncthreads();

  // Bulk async 1D store SMEM -> GMEM (contiguous 41472 B, 16B-aligned both sides).
  if (tid == 0){
    uint32_t sa;
    asm("{ .reg .u64 t; cvta.to.shared.u64 t, %1; cvt.u32.u64 %0, t; }"
        : "=r"(sa) : "l"(sout));
    float* gdst = out + ((size_t)blockIdx.y * 16384 + (size_t)t0) * NCOL;
    asm volatile("fence.proxy.async.shared::cta;" ::: "memory");
    asm volatile("cp.async.bulk.global.shared::cta.bulk_group [%0], [%1], %2;"
                 :: "l"(gdst), "r"(sa), "r"((uint32_t)(TPB * NCOL * 4)) : "memory");
    asm volatile("cp.async.bulk.commit_group;" ::: "memory");
    asm volatile("cp.async.bulk.wait_group 0;" ::: "memory");
  }
}

extern "C" void kernel_launch(void* const* d_in, const int* in_sizes, int n_in,
                              void* d_out, int out_size){
  (void)in_sizes; (void)n_in; (void)out_size;
  const float* x = (const float*)d_in[0];
  float* out = (float*)d_out;
  dim3 grid(16384 / TPB, 16);
  mel_kernel<<<grid, TPB>>>(x, out);
}